// round 16
// baseline (speedup 1.0000x reference)
#include <cuda_runtime.h>
#include <cuda_fp16.h>

#define BATCH 1024
#define LOG2E 1.4426950408889634f
#define NBLK 256

// ---------------- device scratch (no allocations allowed) ----------------
__device__ float g_h2[BATCH * 128];    // after layer 2 (pre-BN)
__device__ float g_sum[128];           // per-col sum of h2 (zeroed at end)
__device__ float g_sq[128];            // per-col sum of h2^2
__device__ uint4 g_Mh[50 * BATCH];     // M * log2e as 5 halfs (+pad), f-major
__device__ unsigned g_bar_count = 0;
__device__ unsigned g_bar_gen = 0;

__device__ __forceinline__ float lrelu(float v) { return fmaxf(v, 0.2f * v); }

// Grid-wide barrier (all NBLK blocks resident by construction).
__device__ __forceinline__ void grid_barrier() {
    __syncthreads();
    if (threadIdx.x == 0) {
        __threadfence();
        const unsigned gen = *(volatile unsigned*)&g_bar_gen;
        if (atomicAdd(&g_bar_count, 1u) == NBLK - 1u) {
            atomicExch(&g_bar_count, 0u);
            __threadfence();
            atomicAdd(&g_bar_gen, 1u);
        } else {
            while (*(volatile unsigned*)&g_bar_gen == gen) __nanosleep(64);
        }
        __threadfence();
    }
    __syncthreads();
}

// ---------------- shared memory union (27.6 KB max, k4 phase) ------------
struct SmemK12 { float xs[4][128]; float h1s[4][256]; float p2[4][128]; };
struct SmemK3  { float hb[4][128]; float h3s[4][64]; float avs[4][64];
                 float hhs[4][64]; float pP[4][4][64]; float Mst[4][250]; };
struct SmemK4  { __half2 sA[10][5][64]; __half sJ[10][5][64]; float red[16][132]; };

__global__ void __launch_bounds__(256, 2)
fused_all(const float* __restrict__ x,
          const float* __restrict__ W1, const float* __restrict__ b1,
          const float* __restrict__ W2, const float* __restrict__ b2,
          const float* __restrict__ gamma, const float* __restrict__ beta,
          const float* __restrict__ W3, const float* __restrict__ b3,
          const float* __restrict__ Wv, const float* __restrict__ bv,
          const float* __restrict__ Wo, const float* __restrict__ bo,
          const float* __restrict__ T,
          const float* __restrict__ Ws, const float* __restrict__ bs,
          float* __restrict__ out) {
    __shared__ __align__(16) unsigned char smem_raw[sizeof(SmemK4)];
    const int t  = threadIdx.x;
    const int bx = blockIdx.x;

    // ===================== phase 1: k12 (4 rows/block) ===================
    {
        SmemK12& S = *reinterpret_cast<SmemK12*>(smem_raw);
        const int r0 = bx * 4;
        for (int n = t; n < 512; n += 256)
            S.xs[n >> 7][n & 127] = x[(r0 + (n >> 7)) * 128 + (n & 127)];
        __syncthreads();

        // stage 1: thread t owns column t (of 256), all 4 rows
        {
            float acc[4] = {0.f, 0.f, 0.f, 0.f};
#pragma unroll 16
            for (int k4 = 0; k4 < 128; k4 += 4) {
                const float w0 = W1[(k4 + 0) * 256 + t];
                const float w1 = W1[(k4 + 1) * 256 + t];
                const float w2 = W1[(k4 + 2) * 256 + t];
                const float w3 = W1[(k4 + 3) * 256 + t];
#pragma unroll
                for (int r = 0; r < 4; r++) {
                    const float4 xv = *(const float4*)&S.xs[r][k4];
                    acc[r] = fmaf(xv.x, w0, acc[r]);
                    acc[r] = fmaf(xv.y, w1, acc[r]);
                    acc[r] = fmaf(xv.z, w2, acc[r]);
                    acc[r] = fmaf(xv.w, w3, acc[r]);
                }
            }
            const float bb = b1[t];
#pragma unroll
            for (int r = 0; r < 4; r++) S.h1s[r][t] = lrelu(acc[r] + bb);
        }
        __syncthreads();

        // stage 2 (K-split): thread -> (col c of 128, k-half ks), 4 rows
        {
            const int c = t & 127, ks = t >> 7;
            const int kb = ks * 128;
            float acc[4] = {0.f, 0.f, 0.f, 0.f};
#pragma unroll 16
            for (int k4 = 0; k4 < 128; k4 += 4) {
                const float w0 = W2[(kb + k4 + 0) * 128 + c];
                const float w1 = W2[(kb + k4 + 1) * 128 + c];
                const float w2 = W2[(kb + k4 + 2) * 128 + c];
                const float w3 = W2[(kb + k4 + 3) * 128 + c];
#pragma unroll
                for (int r = 0; r < 4; r++) {
                    const float4 hv = *(const float4*)&S.h1s[r][kb + k4];
                    acc[r] = fmaf(hv.x, w0, acc[r]);
                    acc[r] = fmaf(hv.y, w1, acc[r]);
                    acc[r] = fmaf(hv.z, w2, acc[r]);
                    acc[r] = fmaf(hv.w, w3, acc[r]);
                }
            }
            if (ks == 1) {
#pragma unroll
                for (int r = 0; r < 4; r++) S.p2[r][c] = acc[r];
            }
            __syncthreads();
            if (ks == 0) {
                const float bb = b2[c];
                float s = 0.f, q = 0.f;
#pragma unroll
                for (int r = 0; r < 4; r++) {
                    const float v = acc[r] + S.p2[r][c] + bb;
                    g_h2[(r0 + r) * 128 + c] = v;
                    s += v;
                    q = fmaf(v, v, q);
                }
                atomicAdd(&g_sum[c], s);
                atomicAdd(&g_sq[c], q);
            }
        }
    }
    grid_barrier();

    // ===================== phase 2: k3 (4 rows/block) ====================
    {
        SmemK3& S = *reinterpret_cast<SmemK3*>(smem_raw);
        const int r0 = bx * 4;
#pragma unroll
        for (int qq = 0; qq < 2; qq++) {
            const int e = t + 256 * qq;
            const int r = e >> 7, c = e & 127;
            const float v   = g_h2[(r0 + r) * 128 + c];
            const float mu  = g_sum[c] * (1.f / BATCH);
            const float var = g_sq[c] * (1.f / BATCH) - mu * mu;
            const float rs  = rsqrtf(var + 1e-5f);
            S.hb[r][c] = lrelu(fmaf((v - mu) * rs, gamma[c], beta[c]));
        }
        __syncthreads();

        const int c  = t & 63;
        const int kq = t >> 6;           // k-quarter / combine row

        // stage A: h3 = lrelu(hb @ W3 + b3), K=128 split 4x32
        {
            float acc[4] = {0.f, 0.f, 0.f, 0.f};
            const int kb = kq * 32;
#pragma unroll 8
            for (int k = kb; k < kb + 32; k++) {
                const float w = W3[k * 64 + c];
#pragma unroll
                for (int r = 0; r < 4; r++) acc[r] = fmaf(S.hb[r][k], w, acc[r]);
            }
#pragma unroll
            for (int r = 0; r < 4; r++) S.pP[kq][r][c] = acc[r];
        }
        __syncthreads();
        S.h3s[kq][c] = lrelu(b3[c] + S.pP[0][kq][c] + S.pP[1][kq][c]
                             + S.pP[2][kq][c] + S.pP[3][kq][c]);
        __syncthreads();

        // stage B: av = h3 @ Wv + bv, K=64 split 4x16
        {
            float acc[4] = {0.f, 0.f, 0.f, 0.f};
            const int kb = kq * 16;
#pragma unroll 8
            for (int k = kb; k < kb + 16; k++) {
                const float w = Wv[k * 64 + c];
#pragma unroll
                for (int r = 0; r < 4; r++) acc[r] = fmaf(S.h3s[r][k], w, acc[r]);
            }
#pragma unroll
            for (int r = 0; r < 4; r++) S.pP[kq][r][c] = acc[r];
        }
        __syncthreads();
        S.avs[kq][c] = bv[c] + S.pP[0][kq][c] + S.pP[1][kq][c]
                     + S.pP[2][kq][c] + S.pP[3][kq][c];
        __syncthreads();

        // stage C: hh = h3 + av @ Wo + bo, K=64 split 4x16
        {
            float acc[4] = {0.f, 0.f, 0.f, 0.f};
            const int kb = kq * 16;
#pragma unroll 8
            for (int k = kb; k < kb + 16; k++) {
                const float w = Wo[k * 64 + c];
#pragma unroll
                for (int r = 0; r < 4; r++) acc[r] = fmaf(S.avs[r][k], w, acc[r]);
            }
#pragma unroll
            for (int r = 0; r < 4; r++) S.pP[kq][r][c] = acc[r];
        }
        __syncthreads();
        S.hhs[kq][c] = bo[c] + S.h3s[kq][c] + S.pP[0][kq][c] + S.pP[1][kq][c]
                     + S.pP[2][kq][c] + S.pP[3][kq][c];
        __syncthreads();

        if (t < 128) {                   // score base: one warp per row
            const int r = t >> 5, l = t & 31;
            float v = S.hhs[r][l] * Ws[l] + S.hhs[r][l + 32] * Ws[l + 32];
#pragma unroll
            for (int o = 16; o > 0; o >>= 1) v += __shfl_down_sync(0xffffffffu, v, o);
            if (l == 0) out[r0 + r] = v + bs[0];
        }

        if (t < 250) {                   // M = hh @ T (pre-scaled by log2 e)
            float acc[4] = {0.f, 0.f, 0.f, 0.f};
#pragma unroll 8
            for (int k = 0; k < 64; k++) {
                const float w = T[k * 250 + t];
#pragma unroll
                for (int r = 0; r < 4; r++) acc[r] = fmaf(S.hhs[r][k], w, acc[r]);
            }
#pragma unroll
            for (int r = 0; r < 4; r++) S.Mst[r][t] = acc[r] * LOG2E;
        }
        __syncthreads();

        for (int idx = t; idx < 200; idx += 256) {
            const int r = idx / 50, f = idx % 50;
            __half2 h01 = __floats2half2_rn(S.Mst[r][5 * f + 0], S.Mst[r][5 * f + 1]);
            __half2 h23 = __floats2half2_rn(S.Mst[r][5 * f + 2], S.Mst[r][5 * f + 3]);
            __half2 h4p = __floats2half2_rn(S.Mst[r][5 * f + 4], 0.f);
            uint4 v;
            v.x = *reinterpret_cast<const unsigned*>(&h01);
            v.y = *reinterpret_cast<const unsigned*>(&h23);
            v.z = *reinterpret_cast<const unsigned*>(&h4p);
            v.w = 0u;
            g_Mh[f * BATCH + r0 + r] = v;
        }
    }
    grid_barrier();

    // ===================== phase 3: k4 (680 tasks over 256 blocks) =======
    {
        SmemK4& S = *reinterpret_cast<SmemK4*>(smem_raw);
        const int ti = t >> 4, tj = t & 15;

        // diag lane masks (task-independent)
        __half2 dmask[4][2];
#pragma unroll
        for (int a = 0; a < 4; a++)
#pragma unroll
            for (int bp = 0; bp < 2; bp++)
                dmask[a][bp] = __floats2half2_rn(
                    (ti * 4 + a) > (tj * 4 + 2 * bp) ? 1.f : 0.f,
                    (ti * 4 + a) > (tj * 4 + 2 * bp + 1) ? 1.f : 0.f);

        for (int task = bx; task < 680; task += NBLK) {
            const int fg = task / 136;
            int u = task % 136, ti_s = 0;
            while (u >= 16 - ti_s) { u -= 16 - ti_s; ti_s++; }
            const int tj_s = ti_s + u;
            const int I0 = ti_s * 64, J0 = tj_s * 64;
            const bool diag = (ti_s == tj_s);

            __syncthreads();             // protect smem reuse across tasks
            const uint4* __restrict__ Mh = g_Mh + fg * 10 * BATCH;
            for (int idx = t; idx < 640; idx += 256) {
                const int ff = idx >> 6, r = idx & 63;
                const uint4 vI = Mh[ff * BATCH + I0 + r];
                const __half2 a01 = *reinterpret_cast<const __half2*>(&vI.x);
                const __half2 a23 = *reinterpret_cast<const __half2*>(&vI.y);
                const __half2 a4  = *reinterpret_cast<const __half2*>(&vI.z);
                S.sA[ff][0][r] = __half2half2(__low2half(a01));
                S.sA[ff][1][r] = __half2half2(__high2half(a01));
                S.sA[ff][2][r] = __half2half2(__low2half(a23));
                S.sA[ff][3][r] = __half2half2(__high2half(a23));
                S.sA[ff][4][r] = __half2half2(__low2half(a4));
                const uint4 vJ = Mh[ff * BATCH + J0 + r];
                const __half2 j01 = *reinterpret_cast<const __half2*>(&vJ.x);
                const __half2 j23 = *reinterpret_cast<const __half2*>(&vJ.y);
                const __half2 j4  = *reinterpret_cast<const __half2*>(&vJ.z);
                S.sJ[ff][0][r] = __low2half(j01);
                S.sJ[ff][1][r] = __high2half(j01);
                S.sJ[ff][2][r] = __low2half(j23);
                S.sJ[ff][3][r] = __high2half(j23);
                S.sJ[ff][4][r] = __low2half(j4);
            }
            __syncthreads();

            float raccW[4] = {0.f, 0.f, 0.f, 0.f};
            float caccW[4] = {0.f, 0.f, 0.f, 0.f};

#pragma unroll 1
            for (int ff = 0; ff < 10; ff++) {
                __half2 mA[4][5], mJ[2][5];
#pragma unroll
                for (int d = 0; d < 5; d++) {
                    const uint4 va = *reinterpret_cast<const uint4*>(&S.sA[ff][d][ti * 4]);
                    mA[0][d] = *reinterpret_cast<const __half2*>(&va.x);
                    mA[1][d] = *reinterpret_cast<const __half2*>(&va.y);
                    mA[2][d] = *reinterpret_cast<const __half2*>(&va.z);
                    mA[3][d] = *reinterpret_cast<const __half2*>(&va.w);
                    const uint2 vj = *reinterpret_cast<const uint2*>(&S.sJ[ff][d][tj * 4]);
                    mJ[0][d] = *reinterpret_cast<const __half2*>(&vj.x);
                    mJ[1][d] = *reinterpret_cast<const __half2*>(&vj.y);
                }

                __half2 racc2[4], cacc2[2];
#pragma unroll
                for (int a = 0; a < 4; a++) racc2[a] = __floats2half2_rn(0.f, 0.f);
#pragma unroll
                for (int bp = 0; bp < 2; bp++) cacc2[bp] = __floats2half2_rn(0.f, 0.f);

                if (!diag) {
#pragma unroll
                    for (int a = 0; a < 4; a++) {
#pragma unroll
                        for (int bp = 0; bp < 2; bp++) {
                            const __half2 d0 = __hsub2(mA[a][0], mJ[bp][0]);
                            const __half2 d1 = __hsub2(mA[a][1], mJ[bp][1]);
                            const __half2 d2 = __hsub2(mA[a][2], mJ[bp][2]);
                            const __half2 d3 = __hsub2(mA[a][3], mJ[bp][3]);
                            const __half2 d4 = __hsub2(mA[a][4], mJ[bp][4]);
                            __half2 s = __hadd2(__habs2(d0), __habs2(d1));
                            const __half2 s2 = __hadd2(__habs2(d2), __habs2(d3));
                            s = __hadd2(s, s2);
                            s = __hadd2(s, __habs2(d4));
                            const __half2 e = h2exp2(__hneg2(s));
                            racc2[a]  = __hadd2(racc2[a], e);
                            cacc2[bp] = __hadd2(cacc2[bp], e);
                        }
                    }
                } else {
#pragma unroll
                    for (int a = 0; a < 4; a++) {
#pragma unroll
                        for (int bp = 0; bp < 2; bp++) {
                            const __half2 d0 = __hsub2(mA[a][0], mJ[bp][0]);
                            const __half2 d1 = __hsub2(mA[a][1], mJ[bp][1]);
                            const __half2 d2 = __hsub2(mA[a][2], mJ[bp][2]);
                            const __half2 d3 = __hsub2(mA[a][3], mJ[bp][3]);
                            const __half2 d4 = __hsub2(mA[a][4], mJ[bp][4]);
                            __half2 s = __hadd2(__habs2(d0), __habs2(d1));
                            const __half2 s2 = __hadd2(__habs2(d2), __habs2(d3));
                            s = __hadd2(s, s2);
                            s = __hadd2(s, __habs2(d4));
                            __half2 e = h2exp2(__hneg2(s));
                            e = __hmul2(e, dmask[a][bp]);
                            racc2[a]  = __hadd2(racc2[a], e);
                            cacc2[bp] = __hadd2(cacc2[bp], e);
                        }
                    }
                }
                const float wf = Ws[64 + fg * 10 + ff];
#pragma unroll
                for (int a = 0; a < 4; a++) {
                    const float2 fr = __half22float2(racc2[a]);
                    raccW[a] = fmaf(fr.x + fr.y, wf, raccW[a]);
                }
#pragma unroll
                for (int bp = 0; bp < 2; bp++) {
                    const float2 fc = __half22float2(cacc2[bp]);
                    caccW[2 * bp]     = fmaf(fc.x, wf, caccW[2 * bp]);
                    caccW[2 * bp + 1] = fmaf(fc.y, wf, caccW[2 * bp + 1]);
                }
            }

            __syncthreads();
#pragma unroll
            for (int a = 0; a < 4; a++) S.red[tj][ti * 4 + a] = raccW[a];
#pragma unroll
            for (int b = 0; b < 4; b++) S.red[ti][64 + tj * 4 + b] = caccW[b];
            __syncthreads();

            if (t < 128) {
                float s = 0.f;
#pragma unroll
                for (int g = 0; g < 16; g++) s += S.red[g][t];
                const int target = (t < 64) ? (I0 + t) : (J0 + t - 64);
                atomicAdd(&out[target], s);
            }
        }

        // re-zero BN stat accumulators for the NEXT graph replay
        // (no one reads g_sum/g_sq in this phase; replays are ordered).
        if (bx == 0 && t < 128) {
            g_sum[t] = 0.f;
            g_sq[t]  = 0.f;
        }
    }
}

// ---------------- launcher ----------------
extern "C" void kernel_launch(void* const* d_in, const int* in_sizes, int n_in,
                              void* d_out, int out_size) {
    const float* x     = (const float*)d_in[0];
    const float* W1    = (const float*)d_in[1];
    const float* b1    = (const float*)d_in[2];
    const float* W2    = (const float*)d_in[3];
    const float* b2    = (const float*)d_in[4];
    const float* gamma = (const float*)d_in[5];
    const float* beta  = (const float*)d_in[6];
    const float* W3    = (const float*)d_in[7];
    const float* b3    = (const float*)d_in[8];
    const float* Wv    = (const float*)d_in[9];
    const float* bv    = (const float*)d_in[10];
    const float* Wo    = (const float*)d_in[11];
    const float* bo    = (const float*)d_in[12];
    const float* T     = (const float*)d_in[13];
    const float* Ws    = (const float*)d_in[14];
    const float* bs    = (const float*)d_in[15];
    float* out = (float*)d_out;

    fused_all<<<NBLK, 256>>>(x, W1, b1, W2, b2, gamma, beta, W3, b3,
                             Wv, bv, Wo, bo, T, Ws, bs, out);
}

// round 17
// speedup vs baseline: 1.8843x; 1.8843x over previous
#include <cuda_runtime.h>
#include <cuda_fp16.h>

#define BATCH 1024
#define LOG2E 1.4426950408889634f

// ---------------- device scratch (no allocations allowed) ----------------
__device__ float g_h2[BATCH * 128];    // after layer 2 (pre-BN)
__device__ float g_sum[128];           // per-col sum of h2 (zeroed by k4 tail)
__device__ float g_sq[128];            // per-col sum of h2^2
__device__ uint4 g_Mh[50 * BATCH];     // M * log2e as 5 halfs (+pad), f-major

__device__ __forceinline__ float lrelu(float v) { return fmaxf(v, 0.2f * v); }

// ---- K12: fused  h1 = lrelu(x@W1+b1) ;  h2 = h1@W2+b2  (+ BN partials) ---
// (R14-verified: scalar streaming, unroll 16, reg cap 128, stage-2 K-split)
__global__ void __launch_bounds__(256, 2) k12_gemm(const float* __restrict__ x,
                                                   const float* __restrict__ W1,
                                                   const float* __restrict__ b1,
                                                   const float* __restrict__ W2,
                                                   const float* __restrict__ b2) {
    __shared__ float xs[4][128];
    __shared__ float h1s[4][256];
    __shared__ float p2[4][128];       // stage-2 partials (k-half 1)
    const int t  = threadIdx.x;
    const int r0 = blockIdx.x * 4;

    for (int n = t; n < 512; n += 256)
        xs[n >> 7][n & 127] = x[(r0 + (n >> 7)) * 128 + (n & 127)];
    __syncthreads();

    // ---- stage 1: thread t owns column t (of 256), all 4 rows ----
    {
        float acc[4] = {0.f, 0.f, 0.f, 0.f};
#pragma unroll 16
        for (int k4 = 0; k4 < 128; k4 += 4) {
            const float w0 = W1[(k4 + 0) * 256 + t];
            const float w1 = W1[(k4 + 1) * 256 + t];
            const float w2 = W1[(k4 + 2) * 256 + t];
            const float w3 = W1[(k4 + 3) * 256 + t];
#pragma unroll
            for (int r = 0; r < 4; r++) {
                const float4 xv = *(const float4*)&xs[r][k4];
                acc[r] = fmaf(xv.x, w0, acc[r]);
                acc[r] = fmaf(xv.y, w1, acc[r]);
                acc[r] = fmaf(xv.z, w2, acc[r]);
                acc[r] = fmaf(xv.w, w3, acc[r]);
            }
        }
        const float bb = b1[t];
#pragma unroll
        for (int r = 0; r < 4; r++) h1s[r][t] = lrelu(acc[r] + bb);
    }
    __syncthreads();

    // ---- stage 2 (K-split): thread -> (col c of 128, k-half ks), 4 rows --
    {
        const int c = t & 127, ks = t >> 7;
        const int kb = ks * 128;
        float acc[4] = {0.f, 0.f, 0.f, 0.f};
#pragma unroll 16
        for (int k4 = 0; k4 < 128; k4 += 4) {
            const float w0 = W2[(kb + k4 + 0) * 128 + c];
            const float w1 = W2[(kb + k4 + 1) * 128 + c];
            const float w2 = W2[(kb + k4 + 2) * 128 + c];
            const float w3 = W2[(kb + k4 + 3) * 128 + c];
#pragma unroll
            for (int r = 0; r < 4; r++) {
                const float4 hv = *(const float4*)&h1s[r][kb + k4];
                acc[r] = fmaf(hv.x, w0, acc[r]);
                acc[r] = fmaf(hv.y, w1, acc[r]);
                acc[r] = fmaf(hv.z, w2, acc[r]);
                acc[r] = fmaf(hv.w, w3, acc[r]);
            }
        }
        if (ks == 1) {
#pragma unroll
            for (int r = 0; r < 4; r++) p2[r][c] = acc[r];
        }
        __syncthreads();
        if (ks == 0) {
            const float bb = b2[c];
            float s = 0.f, q = 0.f;
#pragma unroll
            for (int r = 0; r < 4; r++) {
                const float v = acc[r] + p2[r][c] + bb;
                g_h2[(r0 + r) * 128 + c] = v;
                s += v;
                q = fmaf(v, v, q);
            }
            atomicAdd(&g_sum[c], s);
            atomicAdd(&g_sq[c], q);
        }
    }
}

// ---- K3: BN+lrelu -> layer3 -> attention -> M (fp16, pre-scaled) --------
// Launched with PDL: syncs on k12 completion just before reading g_h2.
__global__ void __launch_bounds__(256, 2) k3_feat(const float* __restrict__ gamma,
                                                  const float* __restrict__ beta,
                                                  const float* __restrict__ W3,
                                                  const float* __restrict__ b3,
                                                  const float* __restrict__ Wv,
                                                  const float* __restrict__ bv,
                                                  const float* __restrict__ Wo,
                                                  const float* __restrict__ bo,
                                                  const float* __restrict__ T,
                                                  const float* __restrict__ Ws,
                                                  const float* __restrict__ bs,
                                                  float* __restrict__ out) {
    __shared__ float hb[8][128], h3s[8][64], avs[8][64], hhs[8][64];
    __shared__ float pP[4][8][64];     // K-split partials (8KB)
    __shared__ float Mst[8][250];
    const int t  = threadIdx.x;
    const int r0 = blockIdx.x * 8;

#if __CUDA_ARCH__ >= 900
    cudaGridDependencySynchronize();   // wait for k12's g_h2/g_sum/g_sq
#endif

#pragma unroll
    for (int qq = 0; qq < 4; qq++) {
        const int e = t + 256 * qq;
        const int r = e >> 7, c = e & 127;
        const float v   = g_h2[(r0 + r) * 128 + c];
        const float mu  = g_sum[c] * (1.f / BATCH);
        const float var = g_sq[c] * (1.f / BATCH) - mu * mu;
        const float rs  = rsqrtf(var + 1e-5f);
        hb[r][c] = lrelu(fmaf((v - mu) * rs, gamma[c], beta[c]));
    }
    __syncthreads();

    const int c  = t & 63;
    const int kq = t >> 6;               // k-quarter / combine row-group

    // ---- stage A: h3 = lrelu(hb @ W3 + b3), K=128 split in 4x32 ----
    {
        float acc[8] = {0,0,0,0,0,0,0,0};
        const int kb = kq * 32;
#pragma unroll 8
        for (int k = kb; k < kb + 32; k++) {
            const float w = W3[k * 64 + c];
#pragma unroll
            for (int r = 0; r < 8; r++) acc[r] = fmaf(hb[r][k], w, acc[r]);
        }
#pragma unroll
        for (int r = 0; r < 8; r++) pP[kq][r][c] = acc[r];
    }
    __syncthreads();
    {
#pragma unroll
        for (int rr = 0; rr < 2; rr++) {
            const int r = 2 * kq + rr;
            const float s = b3[c] + pP[0][r][c] + pP[1][r][c]
                          + pP[2][r][c] + pP[3][r][c];
            h3s[r][c] = lrelu(s);
        }
    }
    __syncthreads();

    // ---- stage B: av = h3 @ Wv + bv, K=64 split in 4x16 ----
    {
        float acc[8] = {0,0,0,0,0,0,0,0};
        const int kb = kq * 16;
#pragma unroll 8
        for (int k = kb; k < kb + 16; k++) {
            const float w = Wv[k * 64 + c];
#pragma unroll
            for (int r = 0; r < 8; r++) acc[r] = fmaf(h3s[r][k], w, acc[r]);
        }
#pragma unroll
        for (int r = 0; r < 8; r++) pP[kq][r][c] = acc[r];
    }
    __syncthreads();
    {
#pragma unroll
        for (int rr = 0; rr < 2; rr++) {
            const int r = 2 * kq + rr;
            avs[r][c] = bv[c] + pP[0][r][c] + pP[1][r][c]
                      + pP[2][r][c] + pP[3][r][c];
        }
    }
    __syncthreads();

    // ---- stage C: hh = h3 + av @ Wo + bo, K=64 split in 4x16 ----
    {
        float acc[8] = {0,0,0,0,0,0,0,0};
        const int kb = kq * 16;
#pragma unroll 8
        for (int k = kb; k < kb + 16; k++) {
            const float w = Wo[k * 64 + c];
#pragma unroll
            for (int r = 0; r < 8; r++) acc[r] = fmaf(avs[r][k], w, acc[r]);
        }
#pragma unroll
        for (int r = 0; r < 8; r++) pP[kq][r][c] = acc[r];
    }
    __syncthreads();
    {
#pragma unroll
        for (int rr = 0; rr < 2; rr++) {
            const int r = 2 * kq + rr;
            hhs[r][c] = bo[c] + h3s[r][c] + pP[0][r][c] + pP[1][r][c]
                      + pP[2][r][c] + pP[3][r][c];
        }
    }
    __syncthreads();

    {   // score base: one warp per row
        const int r = t >> 5, l = t & 31;
        float v = hhs[r][l] * Ws[l] + hhs[r][l + 32] * Ws[l + 32];
#pragma unroll
        for (int o = 16; o > 0; o >>= 1) v += __shfl_down_sync(0xffffffffu, v, o);
        if (l == 0) out[r0 + r] = v + bs[0];
    }

    if (t < 250) {                       // M = hh @ T (pre-scaled by log2 e)
        float acc[8];
#pragma unroll
        for (int r = 0; r < 8; r++) acc[r] = 0.f;
#pragma unroll 8
        for (int k = 0; k < 64; k++) {
            const float w = T[k * 250 + t];
#pragma unroll
            for (int r = 0; r < 8; r++) acc[r] = fmaf(hhs[r][k], w, acc[r]);
        }
#pragma unroll
        for (int r = 0; r < 8; r++) Mst[r][t] = acc[r] * LOG2E;
    }
    __syncthreads();

    for (int idx = t; idx < 400; idx += 256) {
        const int r = idx / 50, f = idx % 50;
        __half2 h01 = __floats2half2_rn(Mst[r][5 * f + 0], Mst[r][5 * f + 1]);
        __half2 h23 = __floats2half2_rn(Mst[r][5 * f + 2], Mst[r][5 * f + 3]);
        __half2 h4p = __floats2half2_rn(Mst[r][5 * f + 4], 0.f);
        uint4 v;
        v.x = *reinterpret_cast<const unsigned*>(&h01);
        v.y = *reinterpret_cast<const unsigned*>(&h23);
        v.z = *reinterpret_cast<const unsigned*>(&h4p);
        v.w = 0u;
        g_Mh[f * BATCH + r0 + r] = v;
    }
}

// ------- K4: MBD, symmetric pairs, fp16x2 + vectorized LDS (R15) ---------
// Launched with PDL: independent preamble (tile decode, masks) runs before
// the dependency sync; g_Mh is read only after the sync.
__global__ void __launch_bounds__(256) k4_mbd(const float* __restrict__ Ws,
                                              float* __restrict__ out) {
    __shared__ __align__(16) __half2 sA[10][5][64];  // (m,m) broadcast pairs
    __shared__ __align__(16) __half  sJ[10][5][64];  // plain halves by j
    __shared__ float red[16][132];

    const int t = threadIdx.x;
    int u = blockIdx.x, ti_s = 0;
    while (u >= 16 - ti_s) { u -= 16 - ti_s; ti_s++; }
    const int tj_s = ti_s + u;
    const int I0 = ti_s * 64, J0 = tj_s * 64;
    const bool diag = (ti_s == tj_s);
    const int ti = t >> 4, tj = t & 15;

    // diag lane masks: allowed iff local i > local j (I0 == J0 on diag)
    __half2 dmask[4][2];
#pragma unroll
    for (int a = 0; a < 4; a++)
#pragma unroll
        for (int bp = 0; bp < 2; bp++)
            dmask[a][bp] = __floats2half2_rn(
                (ti * 4 + a) > (tj * 4 + 2 * bp) ? 1.f : 0.f,
                (ti * 4 + a) > (tj * 4 + 2 * bp + 1) ? 1.f : 0.f);

#if __CUDA_ARCH__ >= 900
    cudaGridDependencySynchronize();   // wait for k3's g_Mh
#endif

    const uint4* __restrict__ Mh = g_Mh + blockIdx.y * 10 * BATCH;
    for (int idx = t; idx < 640; idx += 256) {
        const int ff = idx >> 6, r = idx & 63;
        const uint4 vI = Mh[ff * BATCH + I0 + r];
        const __half2 a01 = *reinterpret_cast<const __half2*>(&vI.x);
        const __half2 a23 = *reinterpret_cast<const __half2*>(&vI.y);
        const __half2 a4  = *reinterpret_cast<const __half2*>(&vI.z);
        sA[ff][0][r] = __half2half2(__low2half(a01));
        sA[ff][1][r] = __half2half2(__high2half(a01));
        sA[ff][2][r] = __half2half2(__low2half(a23));
        sA[ff][3][r] = __half2half2(__high2half(a23));
        sA[ff][4][r] = __half2half2(__low2half(a4));
        const uint4 vJ = Mh[ff * BATCH + J0 + r];
        const __half2 j01 = *reinterpret_cast<const __half2*>(&vJ.x);
        const __half2 j23 = *reinterpret_cast<const __half2*>(&vJ.y);
        const __half2 j4  = *reinterpret_cast<const __half2*>(&vJ.z);
        sJ[ff][0][r] = __low2half(j01);
        sJ[ff][1][r] = __high2half(j01);
        sJ[ff][2][r] = __low2half(j23);
        sJ[ff][3][r] = __high2half(j23);
        sJ[ff][4][r] = __low2half(j4);
    }
    __syncthreads();

    float raccW[4] = {0.f, 0.f, 0.f, 0.f};
    float caccW[4] = {0.f, 0.f, 0.f, 0.f};

#pragma unroll 1
    for (int ff = 0; ff < 10; ff++) {
        __half2 mA[4][5], mJ[2][5];
#pragma unroll
        for (int d = 0; d < 5; d++) {
            const uint4 va = *reinterpret_cast<const uint4*>(&sA[ff][d][ti * 4]);
            mA[0][d] = *reinterpret_cast<const __half2*>(&va.x);
            mA[1][d] = *reinterpret_cast<const __half2*>(&va.y);
            mA[2][d] = *reinterpret_cast<const __half2*>(&va.z);
            mA[3][d] = *reinterpret_cast<const __half2*>(&va.w);
            const uint2 vj = *reinterpret_cast<const uint2*>(&sJ[ff][d][tj * 4]);
            mJ[0][d] = *reinterpret_cast<const __half2*>(&vj.x);
            mJ[1][d] = *reinterpret_cast<const __half2*>(&vj.y);
        }

        __half2 racc2[4], cacc2[2];
#pragma unroll
        for (int a = 0; a < 4; a++) racc2[a] = __floats2half2_rn(0.f, 0.f);
#pragma unroll
        for (int bp = 0; bp < 2; bp++) cacc2[bp] = __floats2half2_rn(0.f, 0.f);

        if (!diag) {
#pragma unroll
            for (int a = 0; a < 4; a++) {
#pragma unroll
                for (int bp = 0; bp < 2; bp++) {
                    const __half2 d0 = __hsub2(mA[a][0], mJ[bp][0]);
                    const __half2 d1 = __hsub2(mA[a][1], mJ[bp][1]);
                    const __half2 d2 = __hsub2(mA[a][2], mJ[bp][2]);
                    const __half2 d3 = __hsub2(mA[a][3], mJ[bp][3]);
                    const __half2 d4 = __hsub2(mA[a][4], mJ[bp][4]);
                    __half2 s = __hadd2(__habs2(d0), __habs2(d1));
                    const __half2 s2 = __hadd2(__habs2(d2), __habs2(d3));
                    s = __hadd2(s, s2);
                    s = __hadd2(s, __habs2(d4));
                    const __half2 e = h2exp2(__hneg2(s));
                    racc2[a]  = __hadd2(racc2[a], e);
                    cacc2[bp] = __hadd2(cacc2[bp], e);
                }
            }
        } else {
#pragma unroll
            for (int a = 0; a < 4; a++) {
#pragma unroll
                for (int bp = 0; bp < 2; bp++) {
                    const __half2 d0 = __hsub2(mA[a][0], mJ[bp][0]);
                    const __half2 d1 = __hsub2(mA[a][1], mJ[bp][1]);
                    const __half2 d2 = __hsub2(mA[a][2], mJ[bp][2]);
                    const __half2 d3 = __hsub2(mA[a][3], mJ[bp][3]);
                    const __half2 d4 = __hsub2(mA[a][4], mJ[bp][4]);
                    __half2 s = __hadd2(__habs2(d0), __habs2(d1));
                    const __half2 s2 = __hadd2(__habs2(d2), __habs2(d3));
                    s = __hadd2(s, s2);
                    s = __hadd2(s, __habs2(d4));
                    __half2 e = h2exp2(__hneg2(s));
                    e = __hmul2(e, dmask[a][bp]);
                    racc2[a]  = __hadd2(racc2[a], e);
                    cacc2[bp] = __hadd2(cacc2[bp], e);
                }
            }
        }
        const float wf = Ws[64 + blockIdx.y * 10 + ff];
#pragma unroll
        for (int a = 0; a < 4; a++) {
            const float2 fr = __half22float2(racc2[a]);
            raccW[a] = fmaf(fr.x + fr.y, wf, raccW[a]);
        }
#pragma unroll
        for (int bp = 0; bp < 2; bp++) {
            const float2 fc = __half22float2(cacc2[bp]);
            caccW[2 * bp]     = fmaf(fc.x, wf, caccW[2 * bp]);
            caccW[2 * bp + 1] = fmaf(fc.y, wf, caccW[2 * bp + 1]);
        }
    }

    __syncthreads();
#pragma unroll
    for (int a = 0; a < 4; a++) red[tj][ti * 4 + a] = raccW[a];
#pragma unroll
    for (int b = 0; b < 4; b++) red[ti][64 + tj * 4 + b] = caccW[b];
    __syncthreads();

    if (t < 128) {
        float s = 0.f;
#pragma unroll
        for (int g = 0; g < 16; g++) s += red[g][t];
        const int target = (t < 64) ? (I0 + t) : (J0 + t - 64);
        atomicAdd(&out[target], s);
    }

    // re-zero BN stat accumulators for the NEXT graph replay (k4 is the
    // final node; next replay's k12 follows it in stream order).
    if (blockIdx.x == 0 && blockIdx.y == 0 && t < 128) {
        g_sum[t] = 0.f;
        g_sq[t]  = 0.f;
    }
}

// ---------------- launcher ----------------
extern "C" void kernel_launch(void* const* d_in, const int* in_sizes, int n_in,
                              void* d_out, int out_size) {
    const float* x     = (const float*)d_in[0];
    const float* W1    = (const float*)d_in[1];
    const float* b1    = (const float*)d_in[2];
    const float* W2    = (const float*)d_in[3];
    const float* b2    = (const float*)d_in[4];
    const float* gamma = (const float*)d_in[5];
    const float* beta  = (const float*)d_in[6];
    const float* W3    = (const float*)d_in[7];
    const float* b3    = (const float*)d_in[8];
    const float* Wv    = (const float*)d_in[9];
    const float* bv    = (const float*)d_in[10];
    const float* Wo    = (const float*)d_in[11];
    const float* bo    = (const float*)d_in[12];
    const float* T     = (const float*)d_in[13];
    const float* Ws    = (const float*)d_in[14];
    const float* bs    = (const float*)d_in[15];
    float* out = (float*)d_out;

    k12_gemm<<<256, 256>>>(x, W1, b1, W2, b2);

    cudaLaunchAttribute pdl[1];
    pdl[0].id = cudaLaunchAttributeProgrammaticStreamSerialization;
    pdl[0].val.programmaticStreamSerializationAllowed = 1;

    {   // k3 with PDL overlap into k12's tail
        cudaLaunchConfig_t cfg = {};
        cfg.gridDim  = dim3(128, 1, 1);
        cfg.blockDim = dim3(256, 1, 1);
        cfg.attrs    = pdl;
        cfg.numAttrs = 1;
        cudaLaunchKernelEx(&cfg, k3_feat, gamma, beta, W3, b3, Wv, bv,
                           Wo, bo, T, Ws, bs, out);
    }
    {   // k4 with PDL overlap into k3's tail
        cudaLaunchConfig_t cfg = {};
        cfg.gridDim  = dim3(136, 5, 1);
        cfg.blockDim = dim3(256, 1, 1);
        cfg.attrs    = pdl;
        cfg.numAttrs = 1;
        cudaLaunchKernelEx(&cfg, k4_mbd, Ws, out);
    }
}